// round 7
// baseline (speedup 1.0000x reference)
#include <cuda_runtime.h>
#include <cuda_bf16.h>
#include <math.h>

#define T  8192
#define E  20
#define H1 30
#define H2 50
#define HL 300
#define NT 50
#define G1 (4*H1)   // 120
#define G2 (4*H2)   // 200
#define D2 (2*H1)   // 60
#define D3 (2*H2)   // 100

// ---- scratch (no allocations allowed) ----
// gx1 layout: [t][unit][gate]  (unit-major, 4 gates contiguous -> one LDG.128)
__device__ float g_gx_fw1[T*G1];
__device__ float g_gx_bw1[T*G1];
__device__ float g_l1[T*D2];
// gx2 layout: [t][gate-row j] (as before), pre-scaled by 0.5 for sigmoid rows
__device__ float g_gx_fw2[T*G2];
__device__ float g_gx_bw2[T*G2];
__device__ float g_l2[T*D3];

typedef unsigned long long u64;

__device__ __forceinline__ u64 pk(float lo, float hi) {
    u64 r; asm("mov.b64 %0, {%1, %2};" : "=l"(r) : "f"(lo), "f"(hi)); return r;
}
__device__ __forceinline__ void upk(u64 v, float& lo, float& hi) {
    asm("mov.b64 {%0, %1}, %2;" : "=f"(lo), "=f"(hi) : "l"(v));
}
__device__ __forceinline__ u64 ffma2(u64 a, u64 b, u64 c) {
    u64 d; asm("fma.rn.f32x2 %0, %1, %2, %3;" : "=l"(d) : "l"(a), "l"(b), "l"(c)); return d;
}
__device__ __forceinline__ u64 addx2(u64 a, u64 b) {
    u64 d; asm("add.rn.f32x2 %0, %1, %2;" : "=l"(d) : "l"(a), "l"(b)); return d;
}
__device__ __forceinline__ float tanh_ap(float x) {
    float y; asm("tanh.approx.f32 %0, %1;" : "=f"(y) : "f"(x)); return y;
}

// ============================================================
// Kernel 1: embedding gather + layer-1 input projections.
// New layout: dst[t*G1 + u*4 + q], pre-scaled (x0.5 for sigmoid
// gates q!=2), so sigma(x) = 0.5*tanh(val)+0.5 directly.
// ============================================================
__global__ void k_gx1(const int* __restrict__ x, const float* __restrict__ emb,
                      const float* __restrict__ WihF, const float* __restrict__ bF,
                      const float* __restrict__ WihB, const float* __restrict__ bB) {
    __shared__ float e[E];
    int t = blockIdx.x;
    int j = threadIdx.x;
    if (j < E) e[j] = emb[(size_t)x[t] * E + j];
    __syncthreads();
    if (j < G1) {
        int q = j / H1, u = j % H1;
        float scl = (q == 2) ? 1.f : 0.5f;
        float aF = bF[j], aB = bB[j];
        #pragma unroll
        for (int k = 0; k < E; k++) {
            float ev = e[k];
            aF += WihF[j*E + k] * ev;
            aB += WihB[j*E + k] * ev;
        }
        g_gx_fw1[t*G1 + u*4 + q] = aF * scl;
        g_gx_bw1[(T-1-t)*G1 + u*4 + q] = aB * scl;
    }
}

// ============================================================
// Kernel 2: layer-1 scan, SINGLE WARP per cell.
// lane = unit (u<30); each lane computes ALL 4 gate dots, does
// c/h update locally. No block barrier, no shfl exchange.
// h exchanged via smem ping-pong + __syncwarp.
// gx fetched as one float4 per step (layout [t][u][4]).
// ============================================================
__global__ void __launch_bounds__(32, 1) k_scan1(
    const float* __restrict__ WhhF, const float* __restrict__ h0F, const float* __restrict__ c0F,
    const float* __restrict__ WhhB, const float* __restrict__ h0B, const float* __restrict__ c0B) {
    const bool bw = (blockIdx.x == 1);
    const float* Whh = bw ? WhhB : WhhF;
    const float* h0  = bw ? h0B  : h0F;
    const float* c0  = bw ? c0B  : c0F;
    const float* gx  = bw ? g_gx_bw1 : g_gx_fw1;
    const int off = bw ? H1 : 0;

    __shared__ __align__(16) float h_sh[2][32];

    const int u = threadIdx.x;
    const bool valid = (u < H1);
    const int uu = valid ? u : 0;

    // weights: 4 gate rows x 30, pre-scaled, packed f32x2, padded to 16 u64
    u64 w[4][16];
    #pragma unroll
    for (int q = 0; q < 4; q++) {
        float scl = (q == 2) ? 1.f : 0.5f;
        const float* row = Whh + (q*H1 + uu)*H1;
        #pragma unroll
        for (int k = 0; k < 15; k++) {
            w[q][k] = pk(valid ? scl*row[2*k] : 0.f, valid ? scl*row[2*k+1] : 0.f);
        }
        w[q][15] = pk(0.f, 0.f);
    }

    h_sh[0][u] = valid ? h0[u] : 0.f;
    h_sh[1][u] = 0.f;
    float c = valid ? c0[uu] : 0.f;

    const float4* gx4 = (const float4*)gx;   // index = t*H1 + u
    float4 ga = gx4[uu];
    float4 gb = gx4[H1 + uu];
    const float4* pre = gx4 + 2*H1 + uu;
    float* outp = g_l1 + off + uu;
    __syncwarp();

    #define SCAN1_STEP(HR, HW, GV, PF) do {                                   \
        const ulonglong2* _h8 = (const ulonglong2*)(HR);                      \
        u64 _ai = pk((GV).x, 0.f), _bi = pk(0.f, 0.f);                        \
        u64 _af = pk((GV).y, 0.f), _bf = pk(0.f, 0.f);                        \
        u64 _ag = pk((GV).z, 0.f), _bg = pk(0.f, 0.f);                        \
        u64 _ao = pk((GV).w, 0.f), _bo = pk(0.f, 0.f);                        \
        _Pragma("unroll")                                                     \
        for (int _kk = 0; _kk < 8; _kk++) {                                   \
            ulonglong2 _hv = _h8[_kk];                                        \
            _ai = ffma2(w[0][2*_kk], _hv.x, _ai);                             \
            _bi = ffma2(w[0][2*_kk+1], _hv.y, _bi);                           \
            _af = ffma2(w[1][2*_kk], _hv.x, _af);                             \
            _bf = ffma2(w[1][2*_kk+1], _hv.y, _bf);                           \
            _ag = ffma2(w[2][2*_kk], _hv.x, _ag);                             \
            _bg = ffma2(w[2][2*_kk+1], _hv.y, _bg);                           \
            _ao = ffma2(w[3][2*_kk], _hv.x, _ao);                             \
            _bo = ffma2(w[3][2*_kk+1], _hv.y, _bo);                           \
        }                                                                     \
        PF;                                                                   \
        u64 _si = addx2(_ai, _bi), _sf = addx2(_af, _bf);                     \
        u64 _sg = addx2(_ag, _bg), _so = addx2(_ao, _bo);                     \
        float _l, _h2, _di, _df, _dg, _do;                                    \
        upk(_si, _l, _h2); _di = _l + _h2;                                    \
        upk(_sf, _l, _h2); _df = _l + _h2;                                    \
        upk(_sg, _l, _h2); _dg = _l + _h2;                                    \
        upk(_so, _l, _h2); _do = _l + _h2;                                    \
        float _I = fmaf(0.5f, tanh_ap(_di), 0.5f);                            \
        float _F = fmaf(0.5f, tanh_ap(_df), 0.5f);                            \
        float _G = tanh_ap(_dg);                                              \
        float _O = fmaf(0.5f, tanh_ap(_do), 0.5f);                            \
        c = fmaf(_F, c, _I*_G);                                               \
        float _hn = _O * tanh_ap(c);                                          \
        if (valid) { (HW)[u] = _hn; *outp = _hn; }                            \
        outp += D2;                                                           \
        __syncwarp();                                                         \
    } while (0)

    for (int t = 0; t < T - 2; t += 2) {
        { float4 gv = ga; SCAN1_STEP(h_sh[0], h_sh[1], gv, { ga = *pre; pre += H1; }); }
        { float4 gv = gb; SCAN1_STEP(h_sh[1], h_sh[0], gv, { gb = *pre; pre += H1; }); }
    }
    { float4 gv = ga; SCAN1_STEP(h_sh[0], h_sh[1], gv, {}); }
    { float4 gv = gb; SCAN1_STEP(h_sh[1], h_sh[0], gv, {}); }
    #undef SCAN1_STEP
}

// ============================================================
// Kernel 3: layer-2 input projections (transposed W in shared),
// pre-scaled by 0.5 for sigmoid rows.
// ============================================================
#define GX2_BLOCKS 64
__global__ void __launch_bounds__(256) k_gx2(
    const float* __restrict__ WihF, const float* __restrict__ bF,
    const float* __restrict__ WihB, const float* __restrict__ bB) {
    __shared__ float W[D2 * G2];   // [k][j]
    __shared__ float row[D2];
    const bool bw = (blockIdx.y == 1);
    const float* Wih = bw ? WihB : WihF;
    const float* b   = bw ? bB   : bF;
    float* dst = bw ? g_gx_bw2 : g_gx_fw2;

    for (int i = threadIdx.x; i < G2*D2; i += blockDim.x) {
        int r = i / D2, k = i % D2;
        W[k*G2 + r] = Wih[i];
    }
    int jme = threadIdx.x;
    float bias = (jme < G2) ? b[jme] : 0.f;
    float scl = (jme < G2 && (jme / H2) == 2) ? 1.f : 0.5f;
    __syncthreads();

    const int tpb = T / GX2_BLOCKS;
    const int t0 = blockIdx.x * tpb;
    for (int t = t0; t < t0 + tpb; t++) {
        int src = bw ? (T-1-t) : t;
        __syncthreads();
        for (int i = threadIdx.x; i < D2; i += blockDim.x) row[i] = g_l1[(size_t)src*D2 + i];
        __syncthreads();
        if (jme < G2) {
            float acc = bias;
            #pragma unroll
            for (int k = 0; k < D2; k++) acc += W[k*G2 + jme] * row[k];
            dst[(size_t)t*G2 + jme] = acc * scl;
        }
    }
}

// ============================================================
// Kernel 4: layer-2 scan, (unit, gate-pair) layout with
// {i,g}/{f,o} pairing: each lane forms one product locally
// before the shfl; one fma after shfl. Pre-scaled sigmoid.
// ============================================================
__global__ void __launch_bounds__(128, 1) k_scan2(
    const float* __restrict__ WhhF, const float* __restrict__ h0F, const float* __restrict__ c0F,
    const float* __restrict__ WhhB, const float* __restrict__ h0B, const float* __restrict__ c0B) {
    const bool bw = (blockIdx.x == 1);
    const float* Whh = bw ? WhhB : WhhF;
    const float* h0  = bw ? h0B  : h0F;
    const float* c0  = bw ? c0B  : c0F;
    const float* gx  = bw ? g_gx_bw2 : g_gx_fw2;
    const int off = bw ? H2 : 0;

    __shared__ __align__(16) float h_sh[2][56];

    const int tid = threadIdx.x;
    const int u = tid >> 1;
    const int p = tid & 1;
    const bool valid = (u < H2);
    const int uu = valid ? u : 0;
    // pairing: p=0 -> {i, g}; p=1 -> {f, o}
    const int r0 = p ? (H2 + uu)   : uu;            // f or i  (both sigmoid)
    const int r1 = p ? (3*H2 + uu) : (2*H2 + uu);   // o or g
    const float scl0 = 0.5f;                         // r0 always sigmoid
    const float scl1 = p ? 0.5f : 1.f;               // o sigmoid / g tanh
    // activation of row1: p=0 -> tanh, p=1 -> sigmoid-form
    const float m1 = p ? 0.5f : 1.f;
    const float b1 = p ? 0.5f : 0.f;

    u64 wp0[26], wp1[26];
    #pragma unroll
    for (int k = 0; k < 25; k++) {
        wp0[k] = pk(valid ? scl0*Whh[r0*H2 + 2*k] : 0.f, valid ? scl0*Whh[r0*H2 + 2*k + 1] : 0.f);
        wp1[k] = pk(valid ? scl1*Whh[r1*H2 + 2*k] : 0.f, valid ? scl1*Whh[r1*H2 + 2*k + 1] : 0.f);
    }
    wp0[25] = pk(0.f, 0.f);
    wp1[25] = pk(0.f, 0.f);

    const u64 Z = pk(0.f, 0.f);

    if (tid < 56) {
        h_sh[0][tid] = (tid < H2) ? h0[tid] : 0.f;
        h_sh[1][tid] = 0.f;
    }
    float c = valid ? c0[uu] : 0.f;

    float ga0 = valid ? gx[r0]      : 0.f;
    float ga1 = valid ? gx[r1]      : 0.f;
    float gb0 = valid ? gx[G2 + r0] : 0.f;
    float gb1 = valid ? gx[G2 + r1] : 0.f;
    const float* pre = gx + 2*G2;
    float* outp = g_l2 + off + uu;
    __syncthreads();

    // gx rows already pre-scaled in k_gx2 for the sigmoid rows; r1 for p=0 (g) unscaled. OK.
    #define SCAN2_STEP(HR, HW, GC0, GC1, PF) do {                              \
        const ulonglong2* _h8 = (const ulonglong2*)(HR);                       \
        u64 _a0 = pk((GC0), 0.f), _a1 = Z, _a2 = Z, _a3 = Z;                   \
        u64 _b0 = pk((GC1), 0.f), _b1 = Z, _b2 = Z, _b3 = Z;                   \
        _Pragma("unroll")                                                      \
        for (int _kk = 0; _kk < 13; _kk++) {                                   \
            ulonglong2 _hv = _h8[_kk];                                         \
            if ((_kk & 1) == 0) {                                              \
                _a0 = ffma2(wp0[2*_kk],   _hv.x, _a0);                         \
                _a1 = ffma2(wp0[2*_kk+1], _hv.y, _a1);                         \
                _b0 = ffma2(wp1[2*_kk],   _hv.x, _b0);                         \
                _b1 = ffma2(wp1[2*_kk+1], _hv.y, _b1);                         \
            } else {                                                           \
                _a2 = ffma2(wp0[2*_kk],   _hv.x, _a2);                         \
                _a3 = ffma2(wp0[2*_kk+1], _hv.y, _a3);                         \
                _b2 = ffma2(wp1[2*_kk],   _hv.x, _b2);                         \
                _b3 = ffma2(wp1[2*_kk+1], _hv.y, _b3);                         \
            }                                                                  \
        }                                                                      \
        PF;                                                                    \
        u64 _sa = addx2(addx2(_a0, _a1), addx2(_a2, _a3));                     \
        u64 _sb = addx2(addx2(_b0, _b1), addx2(_b2, _b3));                     \
        float _d0l,_d0h,_d1l,_d1h; upk(_sa,_d0l,_d0h); upk(_sb,_d1l,_d1h);     \
        float _d0 = _d0l + _d0h, _d1 = _d1l + _d1h;                            \
        float _A0 = fmaf(0.5f, tanh_ap(_d0), 0.5f);  /* i or f */              \
        float _A1 = fmaf(m1,   tanh_ap(_d1), b1);    /* g or o */              \
        float _B0 = __shfl_xor_sync(0xFFFFFFFFu, _A0, 1);                      \
        float _B1 = __shfl_xor_sync(0xFFFFFFFFu, _A1, 1);                      \
        /* p=0: I=A0,G=A1,F=B0,O=B1 ; p=1: F=A0,O=A1,I=B0,G=B1 */              \
        float _tloc = _A0 * (p ? c : _A1);   /* F*c  or  I*G (local, early) */ \
        c = p ? fmaf(_B0, _B1, _tloc) : fmaf(_B0, c, _tloc);                   \
        float _hm = p ? _A1 : _B1;            /* O */                          \
        float _hn = _hm * tanh_ap(c);                                          \
        if (valid) {                                                           \
            if (p == 0) (HW)[u] = _hn;                                         \
            else        *outp = _hn;                                           \
        }                                                                      \
        outp += D3;                                                            \
        __syncthreads();                                                       \
    } while (0)

    for (int t = 0; t < T - 2; t += 2) {
        {
            float gc0 = ga0, gc1 = ga1;
            SCAN2_STEP(h_sh[0], h_sh[1], gc0, gc1,
                       { if (valid) { ga0 = pre[r0]; ga1 = pre[r1]; } pre += G2; });
        }
        {
            float gc0 = gb0, gc1 = gb1;
            SCAN2_STEP(h_sh[1], h_sh[0], gc0, gc1,
                       { if (valid) { gb0 = pre[r0]; gb1 = pre[r1]; } pre += G2; });
        }
    }
    SCAN2_STEP(h_sh[0], h_sh[1], ga0, ga1, {});
    SCAN2_STEP(h_sh[1], h_sh[0], gb0, gb1, {});
    #undef SCAN2_STEP
}

// ============================================================
// Kernel 5: final MLP (weights in dynamic shared).
// ============================================================
#define MLP_SMEM ((HL*D3 + NT*HL + D3 + HL) * 4)
__global__ void __launch_bounds__(320, 1) k_mlp(
    const float* __restrict__ W1, const float* __restrict__ b1,
    const float* __restrict__ W2, const float* __restrict__ b2,
    float* __restrict__ out) {
    extern __shared__ float sm[];
    float* W1s  = sm;
    float* W2s  = W1s + HL*D3;
    float* rowS = W2s + NT*HL;
    float* hidS = rowS + D3;

    int tid = threadIdx.x;
    for (int i = tid; i < HL*D3; i += blockDim.x) W1s[i] = W1[i];
    for (int i = tid; i < NT*HL; i += blockDim.x) W2s[i] = W2[i];
    __syncthreads();

    for (int t = blockIdx.x; t < T; t += gridDim.x) {
        if (tid < D3) rowS[tid] = g_l2[(size_t)t*D3 + tid];
        __syncthreads();
        if (tid < HL) {
            float acc = b1[tid];
            const float4* wr = (const float4*)(W1s + tid*D3);
            const float4* r4 = (const float4*)rowS;
            #pragma unroll
            for (int k = 0; k < D3/4; k++) {
                float4 wv = wr[k]; float4 rv = r4[k];
                acc += wv.x*rv.x + wv.y*rv.y + wv.z*rv.z + wv.w*rv.w;
            }
            hidS[tid] = tanhf(acc);
        }
        __syncthreads();
        if (tid < NT) {
            float acc = b2[tid];
            const float4* wr = (const float4*)(W2s + tid*HL);
            const float4* h4 = (const float4*)hidS;
            #pragma unroll
            for (int k = 0; k < HL/4; k++) {
                float4 wv = wr[k]; float4 hv = h4[k];
                acc += wv.x*hv.x + wv.y*hv.y + wv.z*hv.z + wv.w*hv.w;
            }
            out[(size_t)t*NT + tid] = acc;
        }
        __syncthreads();
    }
}

// ============================================================
// launch
// ============================================================
extern "C" void kernel_launch(void* const* d_in, const int* in_sizes, int n_in,
                              void* d_out, int out_size) {
    const int*   x   = (const int*)  d_in[0];
    const float* emb = (const float*)d_in[1];

    const float* fw1_Wih = (const float*)d_in[2];
    const float* fw1_Whh = (const float*)d_in[3];
    const float* fw1_b   = (const float*)d_in[4];
    const float* fw1_h0  = (const float*)d_in[5];
    const float* fw1_c0  = (const float*)d_in[6];

    const float* bw1_Wih = (const float*)d_in[7];
    const float* bw1_Whh = (const float*)d_in[8];
    const float* bw1_b   = (const float*)d_in[9];
    const float* bw1_h0  = (const float*)d_in[10];
    const float* bw1_c0  = (const float*)d_in[11];

    const float* fw2_Wih = (const float*)d_in[12];
    const float* fw2_Whh = (const float*)d_in[13];
    const float* fw2_b   = (const float*)d_in[14];
    const float* fw2_h0  = (const float*)d_in[15];
    const float* fw2_c0  = (const float*)d_in[16];

    const float* bw2_Wih = (const float*)d_in[17];
    const float* bw2_Whh = (const float*)d_in[18];
    const float* bw2_b   = (const float*)d_in[19];
    const float* bw2_h0  = (const float*)d_in[20];
    const float* bw2_c0  = (const float*)d_in[21];

    const float* lin1_W = (const float*)d_in[22];
    const float* lin1_b = (const float*)d_in[23];
    const float* lin2_W = (const float*)d_in[24];
    const float* lin2_b = (const float*)d_in[25];

    cudaFuncSetAttribute(k_mlp, cudaFuncAttributeMaxDynamicSharedMemorySize, MLP_SMEM);

    k_gx1<<<T, 128>>>(x, emb, fw1_Wih, fw1_b, bw1_Wih, bw1_b);
    k_scan1<<<2, 32>>>(fw1_Whh, fw1_h0, fw1_c0, bw1_Whh, bw1_h0, bw1_c0);
    k_gx2<<<dim3(GX2_BLOCKS, 2), 256>>>(fw2_Wih, fw2_b, bw2_Wih, bw2_b);
    k_scan2<<<2, 128>>>(fw2_Whh, fw2_h0, fw2_c0, bw2_Whh, bw2_h0, bw2_c0);
    k_mlp<<<148, 320, MLP_SMEM>>>(lin1_W, lin1_b, lin2_W, lin2_b, (float*)d_out);
}